// round 9
// baseline (speedup 1.0000x reference)
#include <cuda_runtime.h>

#define N_NODES 50000
#define N_EDGES 800000
#define IN_F    64
#define OUT_F   32
#define N_STEPS 20
#define LR      0.1f
#define SLOPE   0.2f
#define FULLMASK 0xFFFFFFFFu
#define NEG_INF  __int_as_float(0xFF800000)

#define SCAN_TPB 1024
#define SCAN_BLOCKS ((N_NODES + SCAN_TPB - 1) / SCAN_TPB)   // 49

// ---------------- scratch (device globals; no allocation allowed) ----------------
__device__ float g_transformed[N_NODES * OUT_F];
__device__ float g_packed[N_EDGES * OUT_F];     // packed neighbor rows (CSR order)
__device__ float g_mu[N_NODES * OUT_F];
__device__ float g_es[2 * N_NODES];   // double-buffered (parity)
__device__ float g_ed[2 * N_NODES];
__device__ int   g_degi[N_NODES];
__device__ int   g_rowstart[N_NODES + 1];
__device__ int   g_fill[N_NODES];
__device__ int   g_bsum[SCAN_BLOCKS];
__device__ int   g_boff[SCAN_BLOCKS];
__device__ int   g_csr_src[N_EDGES];
__device__ int   g_csr_eid[N_EDGES];

__device__ __forceinline__ float leaky(float x) {
    return (x > 0.0f) ? x : SLOPE * x;
}

// ---------------- setup kernels ----------------

__global__ void init_kernel() {
    int i = blockIdx.x * blockDim.x + threadIdx.x;
    if (i < N_NODES) g_degi[i] = 0;
}

// transformed = mu_upper @ W^T. Warp per node (grid-stride), lane = out feature.
__global__ void gemm_kernel(const float* __restrict__ mu_upper,
                            const float* __restrict__ W) {
    __shared__ float Wt[IN_F][OUT_F];   // Wt[k][f] = W[f*IN_F + k]
    for (int i = threadIdx.x; i < IN_F * OUT_F; i += blockDim.x) {
        int k = i >> 5, f = i & 31;
        Wt[k][f] = W[f * IN_F + k];
    }
    __syncthreads();

    int lane = threadIdx.x & 31;
    int warpsPerGrid = (gridDim.x * blockDim.x) >> 5;
    int w0 = (blockIdx.x * blockDim.x + threadIdx.x) >> 5;

    for (int n = w0; n < N_NODES; n += warpsPerGrid) {
        const float* row = mu_upper + n * IN_F;
        float r0 = row[lane];
        float r1 = row[lane + 32];
        float acc = 0.0f;
#pragma unroll
        for (int k = 0; k < 32; ++k)
            acc = fmaf(__shfl_sync(FULLMASK, r0, k), Wt[k][lane], acc);
#pragma unroll
        for (int k = 0; k < 32; ++k)
            acc = fmaf(__shfl_sync(FULLMASK, r1, k), Wt[32 + k][lane], acc);
        g_transformed[n * OUT_F + lane] = acc;
    }
}

__global__ void count_kernel(const int* __restrict__ dst) {
    int e = blockIdx.x * blockDim.x + threadIdx.x;
    if (e >= N_EDGES) return;
    atomicAdd(&g_degi[dst[e]], 1);
}

__global__ void scanA_kernel() {
    __shared__ int warp_sums[32];
    int tid  = threadIdx.x;
    int lane = tid & 31;
    int wid  = tid >> 5;
    int idx  = blockIdx.x * SCAN_TPB + tid;

    int v = (idx < N_NODES) ? g_degi[idx] : 0;
    int x = v;
#pragma unroll
    for (int off = 1; off < 32; off <<= 1) {
        int y = __shfl_up_sync(FULLMASK, x, off);
        if (lane >= off) x += y;
    }
    if (lane == 31) warp_sums[wid] = x;
    __syncthreads();
    if (wid == 0) {
        int w = warp_sums[lane];
#pragma unroll
        for (int off = 1; off < 32; off <<= 1) {
            int y = __shfl_up_sync(FULLMASK, w, off);
            if (lane >= off) w += y;
        }
        warp_sums[lane] = w;
    }
    __syncthreads();
    int incl = x + ((wid > 0) ? warp_sums[wid - 1] : 0);
    if (idx < N_NODES) g_rowstart[idx] = incl - v;
    if (tid == SCAN_TPB - 1) g_bsum[blockIdx.x] = incl;
}

__global__ void scanB_kernel() {
    __shared__ int s[64];
    int t = threadIdx.x;
    int v = (t < SCAN_BLOCKS) ? g_bsum[t] : 0;
    s[t] = v;
    __syncthreads();
#pragma unroll
    for (int off = 1; off < 64; off <<= 1) {
        int x = (t >= off) ? s[t - off] : 0;
        __syncthreads();
        s[t] += x;
        __syncthreads();
    }
    if (t < SCAN_BLOCKS) g_boff[t] = s[t] - v;
    if (t == 63) g_rowstart[N_NODES] = s[63];
}

__global__ void scanC_kernel() {
    int idx = blockIdx.x * blockDim.x + threadIdx.x;
    if (idx >= N_NODES) return;
    int r = g_rowstart[idx] + g_boff[idx >> 10];
    g_rowstart[idx] = r;
    g_fill[idx] = r;
}

__global__ void scatter_kernel(const int* __restrict__ src,
                               const int* __restrict__ dst) {
    int e = blockIdx.x * blockDim.x + threadIdx.x;
    if (e >= N_EDGES) return;
    int pos = atomicAdd(&g_fill[dst[e]], 1);
    g_csr_src[pos] = src[e];
    g_csr_eid[pos] = e;
}

// pack neighbor feature rows contiguously in CSR order (one-time gather).
// 8 threads per CSR position, float4 per thread.
__global__ void pack_kernel() {
    int t = blockIdx.x * blockDim.x + threadIdx.x;
    int i  = t >> 3;
    int fl = t & 7;
    if (i >= N_EDGES) return;
    int s = g_csr_src[i];
    *(float4*)(g_packed + i * OUT_F + fl * 4) =
        *(const float4*)(g_transformed + s * OUT_F + fl * 4);
}

// ---------------- step 0: uniform-alpha top-down + node update (mu0 = 0) --------
// quarter-warp float4: contiguous packed reads, no shuffles in the sum loop.
__global__ void step0_kernel(const float* __restrict__ a_vec) {
    int t = blockIdx.x * blockDim.x + threadIdx.x;
    int n = t >> 5;
    int lane = t & 31;
    if (n >= N_NODES) return;
    int q  = lane >> 3;
    int fl = lane & 7;

    int beg = g_rowstart[n], end = g_rowstart[n + 1];
    int deg = end - beg;

    float4 acc = make_float4(0.f, 0.f, 0.f, 0.f);
    for (int base = 0; base < deg; base += 4) {
        int e = base + q;
        if (e < deg) {
            const float4 r = *(const float4*)(g_packed + (beg + e) * OUT_F + fl * 4);
            acc.x += r.x; acc.y += r.y; acc.z += r.z; acc.w += r.w;
        }
    }
#pragma unroll
    for (int off = 8; off <= 16; off <<= 1) {
        acc.x += __shfl_xor_sync(FULLMASK, acc.x, off);
        acc.y += __shfl_xor_sync(FULLMASK, acc.y, off);
        acc.z += __shfl_xor_sync(FULLMASK, acc.z, off);
        acc.w += __shfl_xor_sync(FULLMASK, acc.w, off);
    }
    float inv = 1.0f / ((float)deg + 1e-8f);
    float4 mh = make_float4(fmaxf(acc.x * inv, 0.f), fmaxf(acc.y * inv, 0.f),
                            fmaxf(acc.z * inv, 0.f), fmaxf(acc.w * inv, 0.f));
    const float4 as = *(const float4*)(a_vec + fl * 4);
    const float4 ad = *(const float4*)(a_vec + OUT_F + fl * 4);
    float ps = -(mh.x * as.x + mh.y * as.y + mh.z * as.z + mh.w * as.w);
    float pd = -(mh.x * ad.x + mh.y * ad.y + mh.z * ad.z + mh.w * ad.w);
#pragma unroll
    for (int off = 1; off <= 4; off <<= 1) {
        ps += __shfl_xor_sync(FULLMASK, ps, off);
        pd += __shfl_xor_sync(FULLMASK, pd, off);
    }
    if (lane == 0) {
        g_es[n] = ps;
        g_ed[n] = pd;
    }
    if (q == 0)
        *(float4*)(g_mu + n * OUT_F + fl * 4) =
            make_float4(LR * mh.x, LR * mh.y, LR * mh.z, LR * mh.w);
}

// ---------------- fused step: softmax + aggregate + node update ----------------
// mode 0: intermediate (writes mu, es/ed[out_par]); mode 1: final outputs.
__global__ void __launch_bounds__(256)
fused_step_kernel(const float* __restrict__ a_vec,
                  int in_par, int out_par, int mode,
                  float* __restrict__ out_mu,
                  float* __restrict__ out_err,
                  float* __restrict__ out_alpha) {
    int t = blockIdx.x * blockDim.x + threadIdx.x;
    int n = t >> 5;
    int lane = t & 31;
    if (n >= N_NODES) return;
    int q  = lane >> 3;
    int fl = lane & 7;

    const float* es_in = g_es + in_par * N_NODES;
    const float* ed_in = g_ed + in_par * N_NODES;

    int beg = g_rowstart[n], end = g_rowstart[n + 1];
    int deg = end - beg;
    float ed_n = ed_in[n];

    float inv;
    float4 acc = make_float4(0.f, 0.f, 0.f, 0.f);

    if (deg <= 64) {
        // -------- score phase: lane per edge, 2-block register cache --------
        int i0 = beg + lane, i1 = i0 + 32;
        int s0 = 0, s1 = 0;
        float sc0 = NEG_INF, sc1 = NEG_INF;
        if (i0 < end) {
            s0 = g_csr_src[i0];
            sc0 = leaky(es_in[s0] + ed_n);
        }
        if (i1 < end) {
            s1 = g_csr_src[i1];
            sc1 = leaky(es_in[s1] + ed_n);
        }
        float mx = fmaxf(sc0, sc1);
#pragma unroll
        for (int off = 16; off > 0; off >>= 1)
            mx = fmaxf(mx, __shfl_xor_sync(FULLMASK, mx, off));
        if (mx == NEG_INF) mx = 0.0f;    // deg==0 guard

        float ev0 = __expf(sc0 - mx);    // inactive lanes -> exp(-inf)=0
        float ev1 = __expf(sc1 - mx);
        float sm = ev0 + ev1;
#pragma unroll
        for (int off = 16; off > 0; off >>= 1)
            sm += __shfl_xor_sync(FULLMASK, sm, off);
        inv = 1.0f / (sm + 1e-8f);

        // -------- accumulate: contiguous packed rows, quarter per edge ------
        if (deg <= 32) {
            for (int base = 0; base < deg; base += 4) {
                int e = base + q;
                float evj = __shfl_sync(FULLMASK, ev0, e & 31);
                if (e < deg) {
                    const float4 r = *(const float4*)(g_packed + (beg + e) * OUT_F + fl * 4);
                    acc.x = fmaf(evj, r.x, acc.x);
                    acc.y = fmaf(evj, r.y, acc.y);
                    acc.z = fmaf(evj, r.z, acc.z);
                    acc.w = fmaf(evj, r.w, acc.w);
                }
            }
        } else {
            for (int base = 0; base < deg; base += 4) {
                int e = base + q;
                int lsel = e & 31;
                float eA = __shfl_sync(FULLMASK, ev0, lsel);
                float eB = __shfl_sync(FULLMASK, ev1, lsel);
                float evj = (e < 32) ? eA : eB;
                if (e < deg) {
                    const float4 r = *(const float4*)(g_packed + (beg + e) * OUT_F + fl * 4);
                    acc.x = fmaf(evj, r.x, acc.x);
                    acc.y = fmaf(evj, r.y, acc.y);
                    acc.z = fmaf(evj, r.z, acc.z);
                    acc.w = fmaf(evj, r.w, acc.w);
                }
            }
        }

        if (mode == 1) {
            if (i0 < end) out_alpha[g_csr_eid[i0]] = ev0 * inv;
            if (i1 < end) out_alpha[g_csr_eid[i1]] = ev1 * inv;
        }
    } else {
        // -------- fallback (deg > 64): strided two-pass --------
        float mx = NEG_INF;
        for (int i = beg + lane; i < end; i += 32) {
            int s = g_csr_src[i];
            mx = fmaxf(mx, leaky(es_in[s] + ed_n));
        }
#pragma unroll
        for (int off = 16; off > 0; off >>= 1)
            mx = fmaxf(mx, __shfl_xor_sync(FULLMASK, mx, off));

        float sm = 0.0f;
        for (int base = beg; base < end; base += 32) {
            int i = base + lane;
            int s = 0;
            float ev = 0.0f;
            if (i < end) {
                s = g_csr_src[i];
                ev = __expf(leaky(es_in[s] + ed_n) - mx);
                sm += ev;
            }
            int cnt = min(32, end - base);
            for (int g = 0; g < cnt; g += 4) {
                int e = g + q;
                float evj = __shfl_sync(FULLMASK, ev, e & 31);
                if (e < cnt) {
                    const float4 r = *(const float4*)(g_packed + (base + e) * OUT_F + fl * 4);
                    acc.x = fmaf(evj, r.x, acc.x);
                    acc.y = fmaf(evj, r.y, acc.y);
                    acc.z = fmaf(evj, r.z, acc.z);
                    acc.w = fmaf(evj, r.w, acc.w);
                }
            }
        }
#pragma unroll
        for (int off = 16; off > 0; off >>= 1)
            sm += __shfl_xor_sync(FULLMASK, sm, off);
        inv = 1.0f / (sm + 1e-8f);

        if (mode == 1) {
            for (int i = beg + lane; i < end; i += 32) {
                int s = g_csr_src[i];
                float ev = __expf(leaky(es_in[s] + ed_n) - mx);
                out_alpha[g_csr_eid[i]] = ev * inv;
            }
        }
    }

    // -------- reduce acc across quarters --------
#pragma unroll
    for (int off = 8; off <= 16; off <<= 1) {
        acc.x += __shfl_xor_sync(FULLMASK, acc.x, off);
        acc.y += __shfl_xor_sync(FULLMASK, acc.y, off);
        acc.z += __shfl_xor_sync(FULLMASK, acc.z, off);
        acc.w += __shfl_xor_sync(FULLMASK, acc.w, off);
    }

    // -------- fused node update (float4 per lane over features fl*4..+3) ----
    int idx4 = n * OUT_F + fl * 4;
    float4 mh = make_float4(fmaxf(acc.x * inv, 0.f), fmaxf(acc.y * inv, 0.f),
                            fmaxf(acc.z * inv, 0.f), fmaxf(acc.w * inv, 0.f));
    float4 mu = *(const float4*)(g_mu + idx4);
    float4 er = make_float4(mu.x - mh.x, mu.y - mh.y, mu.z - mh.z, mu.w - mh.w);

    if (mode == 0) {
        const float4 as = *(const float4*)(a_vec + fl * 4);
        const float4 ad = *(const float4*)(a_vec + OUT_F + fl * 4);
        float ps = er.x * as.x + er.y * as.y + er.z * as.z + er.w * as.w;
        float pd = er.x * ad.x + er.y * ad.y + er.z * ad.z + er.w * ad.w;
#pragma unroll
        for (int off = 1; off <= 4; off <<= 1) {
            ps += __shfl_xor_sync(FULLMASK, ps, off);
            pd += __shfl_xor_sync(FULLMASK, pd, off);
        }
        if (lane == 0) {
            g_es[out_par * N_NODES + n] = ps;
            g_ed[out_par * N_NODES + n] = pd;
        }
        if (q == 0) {
            float4 mun = make_float4(mu.x - LR * er.x, mu.y - LR * er.y,
                                     mu.z - LR * er.z, mu.w - LR * er.w);
            *(float4*)(g_mu + idx4) = mun;
        }
    } else {
        if (q == 0) {
            *(float4*)(out_mu + idx4)  = mu;
            *(float4*)(out_err + idx4) = er;
        }
    }
}

// ---------------- launch ----------------
extern "C" void kernel_launch(void* const* d_in, const int* in_sizes, int n_in,
                              void* d_out, int out_size) {
    const float* mu_upper   = (const float*)d_in[0];
    const float* W          = (const float*)d_in[1];
    const float* a_vec      = (const float*)d_in[2];
    const int*   edge_index = (const int*)d_in[3];
    const int*   src = edge_index;
    const int*   dst = edge_index + N_EDGES;

    float* out       = (float*)d_out;
    float* out_mu    = out;
    float* out_err   = out + N_NODES * OUT_F;
    float* out_alpha = out + 2 * N_NODES * OUT_F;

    const int TPB = 256;
    const int nodeBlocks1 = (N_NODES + TPB - 1) / TPB;
    const int edgeBlocks  = (N_EDGES + TPB - 1) / TPB;
    const int warpNodeBlocks = (N_NODES * 32 + TPB - 1) / TPB;
    const int packBlocks  = (N_EDGES * 8 + TPB - 1) / TPB;

    init_kernel<<<nodeBlocks1, TPB>>>();
    gemm_kernel<<<1024, TPB>>>(mu_upper, W);
    count_kernel<<<edgeBlocks, TPB>>>(dst);
    scanA_kernel<<<SCAN_BLOCKS, SCAN_TPB>>>();
    scanB_kernel<<<1, 64>>>();
    scanC_kernel<<<nodeBlocks1, TPB>>>();
    scatter_kernel<<<edgeBlocks, TPB>>>(src, dst);
    pack_kernel<<<packBlocks, TPB>>>();

    step0_kernel<<<warpNodeBlocks, TPB>>>(a_vec);

    for (int t = 1; t < N_STEPS; ++t) {
        fused_step_kernel<<<warpNodeBlocks, TPB>>>(
            a_vec, (t - 1) & 1, t & 1, 0, nullptr, nullptr, nullptr);
    }
    fused_step_kernel<<<warpNodeBlocks, TPB>>>(
        a_vec, (N_STEPS - 1) & 1, 0, 1, out_mu, out_err, out_alpha);
}

// round 10
// speedup vs baseline: 1.8000x; 1.8000x over previous
#include <cuda_runtime.h>

#define N_NODES 50000
#define N_EDGES 800000
#define IN_F    64
#define OUT_F   32
#define N_STEPS 20
#define LR      0.1f
#define SLOPE   0.2f
#define FULLMASK 0xFFFFFFFFu
#define NEG_INF  __int_as_float(0xFF800000)

#define SCAN_TPB 1024
#define SCAN_BLOCKS ((N_NODES + SCAN_TPB - 1) / SCAN_TPB)   // 49

// ---------------- scratch (device globals; no allocation allowed) ----------------
__device__ float g_transformed[N_NODES * OUT_F];
__device__ float g_mu[N_NODES * OUT_F];
__device__ float g_es[2 * N_NODES];   // double-buffered (parity)
__device__ float g_ed[2 * N_NODES];
__device__ int   g_degi[N_NODES];
__device__ int   g_rowstart[N_NODES + 1];
__device__ int   g_fill[N_NODES];
__device__ int   g_bsum[SCAN_BLOCKS];
__device__ int   g_boff[SCAN_BLOCKS];
__device__ int   g_csr_src[N_EDGES];
__device__ int   g_csr_eid[N_EDGES];

__device__ __forceinline__ float leaky(float x) {
    return (x > 0.0f) ? x : SLOPE * x;
}

// ---------------- setup kernels ----------------

__global__ void init_kernel() {
    int i = blockIdx.x * blockDim.x + threadIdx.x;
    if (i < N_NODES) g_degi[i] = 0;
}

// transformed = mu_upper @ W^T. Warp per node (grid-stride), lane = out feature.
__global__ void gemm_kernel(const float* __restrict__ mu_upper,
                            const float* __restrict__ W) {
    __shared__ float Wt[IN_F][OUT_F];   // Wt[k][f] = W[f*IN_F + k]
    for (int i = threadIdx.x; i < IN_F * OUT_F; i += blockDim.x) {
        int k = i >> 5, f = i & 31;
        Wt[k][f] = W[f * IN_F + k];
    }
    __syncthreads();

    int lane = threadIdx.x & 31;
    int warpsPerGrid = (gridDim.x * blockDim.x) >> 5;
    int w0 = (blockIdx.x * blockDim.x + threadIdx.x) >> 5;

    for (int n = w0; n < N_NODES; n += warpsPerGrid) {
        const float* row = mu_upper + n * IN_F;
        float r0 = row[lane];
        float r1 = row[lane + 32];
        float acc = 0.0f;
#pragma unroll
        for (int k = 0; k < 32; ++k)
            acc = fmaf(__shfl_sync(FULLMASK, r0, k), Wt[k][lane], acc);
#pragma unroll
        for (int k = 0; k < 32; ++k)
            acc = fmaf(__shfl_sync(FULLMASK, r1, k), Wt[32 + k][lane], acc);
        g_transformed[n * OUT_F + lane] = acc;
    }
}

__global__ void count_kernel(const int* __restrict__ dst) {
    int e = blockIdx.x * blockDim.x + threadIdx.x;
    if (e >= N_EDGES) return;
    atomicAdd(&g_degi[dst[e]], 1);
}

__global__ void scanA_kernel() {
    __shared__ int warp_sums[32];
    int tid  = threadIdx.x;
    int lane = tid & 31;
    int wid  = tid >> 5;
    int idx  = blockIdx.x * SCAN_TPB + tid;

    int v = (idx < N_NODES) ? g_degi[idx] : 0;
    int x = v;
#pragma unroll
    for (int off = 1; off < 32; off <<= 1) {
        int y = __shfl_up_sync(FULLMASK, x, off);
        if (lane >= off) x += y;
    }
    if (lane == 31) warp_sums[wid] = x;
    __syncthreads();
    if (wid == 0) {
        int w = warp_sums[lane];
#pragma unroll
        for (int off = 1; off < 32; off <<= 1) {
            int y = __shfl_up_sync(FULLMASK, w, off);
            if (lane >= off) w += y;
        }
        warp_sums[lane] = w;
    }
    __syncthreads();
    int incl = x + ((wid > 0) ? warp_sums[wid - 1] : 0);
    if (idx < N_NODES) g_rowstart[idx] = incl - v;
    if (tid == SCAN_TPB - 1) g_bsum[blockIdx.x] = incl;
}

__global__ void scanB_kernel() {
    __shared__ int s[64];
    int t = threadIdx.x;
    int v = (t < SCAN_BLOCKS) ? g_bsum[t] : 0;
    s[t] = v;
    __syncthreads();
#pragma unroll
    for (int off = 1; off < 64; off <<= 1) {
        int x = (t >= off) ? s[t - off] : 0;
        __syncthreads();
        s[t] += x;
        __syncthreads();
    }
    if (t < SCAN_BLOCKS) g_boff[t] = s[t] - v;
    if (t == 63) g_rowstart[N_NODES] = s[63];
}

__global__ void scanC_kernel() {
    int idx = blockIdx.x * blockDim.x + threadIdx.x;
    if (idx >= N_NODES) return;
    int r = g_rowstart[idx] + g_boff[idx >> 10];
    g_rowstart[idx] = r;
    g_fill[idx] = r;
}

__global__ void scatter_kernel(const int* __restrict__ src,
                               const int* __restrict__ dst) {
    int e = blockIdx.x * blockDim.x + threadIdx.x;
    if (e >= N_EDGES) return;
    int pos = atomicAdd(&g_fill[dst[e]], 1);
    g_csr_src[pos] = src[e];
    g_csr_eid[pos] = e;
}

// ---------------- step 0: uniform-alpha top-down + node update (mu0 = 0) --------
__global__ void step0_kernel(const float* __restrict__ a_vec) {
    int t = blockIdx.x * blockDim.x + threadIdx.x;
    int n = t >> 5;
    int lane = t & 31;
    if (n >= N_NODES) return;
    int q  = lane >> 3;
    int fl = lane & 7;

    int beg = g_rowstart[n], end = g_rowstart[n + 1];
    int deg = end - beg;

    float4 acc = make_float4(0.f, 0.f, 0.f, 0.f);
#pragma unroll 2
    for (int base = 0; base < deg; base += 4) {
        int e = base + q;
        if (e < deg) {
            int s = __ldg(&g_csr_src[beg + e]);
            const float4 r = *(const float4*)(g_transformed + s * OUT_F + fl * 4);
            acc.x += r.x; acc.y += r.y; acc.z += r.z; acc.w += r.w;
        }
    }
#pragma unroll
    for (int off = 8; off <= 16; off <<= 1) {
        acc.x += __shfl_xor_sync(FULLMASK, acc.x, off);
        acc.y += __shfl_xor_sync(FULLMASK, acc.y, off);
        acc.z += __shfl_xor_sync(FULLMASK, acc.z, off);
        acc.w += __shfl_xor_sync(FULLMASK, acc.w, off);
    }
    float inv = 1.0f / ((float)deg + 1e-8f);
    float4 mh = make_float4(fmaxf(acc.x * inv, 0.f), fmaxf(acc.y * inv, 0.f),
                            fmaxf(acc.z * inv, 0.f), fmaxf(acc.w * inv, 0.f));
    const float4 as = *(const float4*)(a_vec + fl * 4);
    const float4 ad = *(const float4*)(a_vec + OUT_F + fl * 4);
    float ps = -(mh.x * as.x + mh.y * as.y + mh.z * as.z + mh.w * as.w);
    float pd = -(mh.x * ad.x + mh.y * ad.y + mh.z * ad.z + mh.w * ad.w);
#pragma unroll
    for (int off = 1; off <= 4; off <<= 1) {
        ps += __shfl_xor_sync(FULLMASK, ps, off);
        pd += __shfl_xor_sync(FULLMASK, pd, off);
    }
    if (lane == 0) {
        g_es[n] = ps;
        g_ed[n] = pd;
    }
    if (q == 0)
        *(float4*)(g_mu + n * OUT_F + fl * 4) =
            make_float4(LR * mh.x, LR * mh.y, LR * mh.z, LR * mh.w);
}

// ---------------- fused step: softmax + aggregate + node update ----------------
// mode 0: intermediate (writes mu, es/ed[out_par]); mode 1: final outputs.
__global__ void __launch_bounds__(256)
fused_step_kernel(const float* __restrict__ a_vec,
                  int in_par, int out_par, int mode,
                  float* __restrict__ out_mu,
                  float* __restrict__ out_err,
                  float* __restrict__ out_alpha) {
    int t = blockIdx.x * blockDim.x + threadIdx.x;
    int n = t >> 5;
    int lane = t & 31;
    if (n >= N_NODES) return;
    int q  = lane >> 3;
    int fl = lane & 7;

    const float* __restrict__ es_in = g_es + in_par * N_NODES;
    const float* __restrict__ ed_in = g_ed + in_par * N_NODES;

    int beg = g_rowstart[n], end = g_rowstart[n + 1];
    int deg = end - beg;
    float ed_n = __ldg(&ed_in[n]);

    float inv;
    float4 acc = make_float4(0.f, 0.f, 0.f, 0.f);

    if (deg <= 64) {
        // -------- score phase: lane per edge, 2-block register cache --------
        int i0 = beg + lane, i1 = i0 + 32;
        int s0 = 0, s1 = 0;
        float sc0 = NEG_INF, sc1 = NEG_INF;
        if (i0 < end) {
            s0 = __ldg(&g_csr_src[i0]);
            sc0 = leaky(__ldg(&es_in[s0]) + ed_n);
        }
        if (i1 < end) {
            s1 = __ldg(&g_csr_src[i1]);
            sc1 = leaky(__ldg(&es_in[s1]) + ed_n);
        }
        float mx = fmaxf(sc0, sc1);
#pragma unroll
        for (int off = 16; off > 0; off >>= 1)
            mx = fmaxf(mx, __shfl_xor_sync(FULLMASK, mx, off));
        if (mx == NEG_INF) mx = 0.0f;    // deg==0 guard

        float ev0 = __expf(sc0 - mx);    // inactive lanes -> exp(-inf)=0
        float ev1 = __expf(sc1 - mx);
        float sm = ev0 + ev1;
#pragma unroll
        for (int off = 16; off > 0; off >>= 1)
            sm += __shfl_xor_sync(FULLMASK, sm, off);
        inv = 1.0f / (sm + 1e-8f);

        // -------- accumulate: 4 edges/iter, quarter per edge, float4/lane ----
        if (deg <= 32) {
#pragma unroll 2
            for (int base = 0; base < deg; base += 4) {
                int e = base + q;
                int   sj  = __shfl_sync(FULLMASK, s0,  e & 31);
                float evj = __shfl_sync(FULLMASK, ev0, e & 31);
                if (e < deg) {
                    const float4 r = *(const float4*)(g_transformed + sj * OUT_F + fl * 4);
                    acc.x = fmaf(evj, r.x, acc.x);
                    acc.y = fmaf(evj, r.y, acc.y);
                    acc.z = fmaf(evj, r.z, acc.z);
                    acc.w = fmaf(evj, r.w, acc.w);
                }
            }
        } else {
#pragma unroll 2
            for (int base = 0; base < deg; base += 4) {
                int e = base + q;
                int lsel = e & 31;
                int   sA = __shfl_sync(FULLMASK, s0,  lsel);
                float eA = __shfl_sync(FULLMASK, ev0, lsel);
                int   sB = __shfl_sync(FULLMASK, s1,  lsel);
                float eB = __shfl_sync(FULLMASK, ev1, lsel);
                int   sj  = (e < 32) ? sA : sB;
                float evj = (e < 32) ? eA : eB;
                if (e < deg) {
                    const float4 r = *(const float4*)(g_transformed + sj * OUT_F + fl * 4);
                    acc.x = fmaf(evj, r.x, acc.x);
                    acc.y = fmaf(evj, r.y, acc.y);
                    acc.z = fmaf(evj, r.z, acc.z);
                    acc.w = fmaf(evj, r.w, acc.w);
                }
            }
        }

        if (mode == 1) {
            if (i0 < end) out_alpha[g_csr_eid[i0]] = ev0 * inv;
            if (i1 < end) out_alpha[g_csr_eid[i1]] = ev1 * inv;
        }
    } else {
        // -------- fallback (deg > 64): strided two-pass --------
        float mx = NEG_INF;
        for (int i = beg + lane; i < end; i += 32) {
            int s = __ldg(&g_csr_src[i]);
            mx = fmaxf(mx, leaky(__ldg(&es_in[s]) + ed_n));
        }
#pragma unroll
        for (int off = 16; off > 0; off >>= 1)
            mx = fmaxf(mx, __shfl_xor_sync(FULLMASK, mx, off));

        float sm = 0.0f;
        for (int base = beg; base < end; base += 32) {
            int i = base + lane;
            int s = 0;
            float ev = 0.0f;
            if (i < end) {
                s = __ldg(&g_csr_src[i]);
                ev = __expf(leaky(__ldg(&es_in[s]) + ed_n) - mx);
                sm += ev;
            }
            int cnt = min(32, end - base);
            for (int g = 0; g < cnt; g += 4) {
                int e = g + q;
                int   sj  = __shfl_sync(FULLMASK, s,  e & 31);
                float evj = __shfl_sync(FULLMASK, ev, e & 31);
                if (e < cnt) {
                    const float4 r = *(const float4*)(g_transformed + sj * OUT_F + fl * 4);
                    acc.x = fmaf(evj, r.x, acc.x);
                    acc.y = fmaf(evj, r.y, acc.y);
                    acc.z = fmaf(evj, r.z, acc.z);
                    acc.w = fmaf(evj, r.w, acc.w);
                }
            }
        }
#pragma unroll
        for (int off = 16; off > 0; off >>= 1)
            sm += __shfl_xor_sync(FULLMASK, sm, off);
        inv = 1.0f / (sm + 1e-8f);

        if (mode == 1) {
            for (int i = beg + lane; i < end; i += 32) {
                int s = __ldg(&g_csr_src[i]);
                float ev = __expf(leaky(__ldg(&es_in[s]) + ed_n) - mx);
                out_alpha[g_csr_eid[i]] = ev * inv;
            }
        }
    }

    // -------- reduce acc across quarters --------
#pragma unroll
    for (int off = 8; off <= 16; off <<= 1) {
        acc.x += __shfl_xor_sync(FULLMASK, acc.x, off);
        acc.y += __shfl_xor_sync(FULLMASK, acc.y, off);
        acc.z += __shfl_xor_sync(FULLMASK, acc.z, off);
        acc.w += __shfl_xor_sync(FULLMASK, acc.w, off);
    }

    // -------- fused node update (float4 per lane over features fl*4..+3) ----
    int idx4 = n * OUT_F + fl * 4;
    float4 mh = make_float4(fmaxf(acc.x * inv, 0.f), fmaxf(acc.y * inv, 0.f),
                            fmaxf(acc.z * inv, 0.f), fmaxf(acc.w * inv, 0.f));
    float4 mu = *(const float4*)(g_mu + idx4);
    float4 er = make_float4(mu.x - mh.x, mu.y - mh.y, mu.z - mh.z, mu.w - mh.w);

    if (mode == 0) {
        const float4 as = *(const float4*)(a_vec + fl * 4);
        const float4 ad = *(const float4*)(a_vec + OUT_F + fl * 4);
        float ps = er.x * as.x + er.y * as.y + er.z * as.z + er.w * as.w;
        float pd = er.x * ad.x + er.y * ad.y + er.z * ad.z + er.w * ad.w;
#pragma unroll
        for (int off = 1; off <= 4; off <<= 1) {
            ps += __shfl_xor_sync(FULLMASK, ps, off);
            pd += __shfl_xor_sync(FULLMASK, pd, off);
        }
        if (lane == 0) {
            g_es[out_par * N_NODES + n] = ps;
            g_ed[out_par * N_NODES + n] = pd;
        }
        if (q == 0) {
            float4 mun = make_float4(mu.x - LR * er.x, mu.y - LR * er.y,
                                     mu.z - LR * er.z, mu.w - LR * er.w);
            *(float4*)(g_mu + idx4) = mun;
        }
    } else {
        if (q == 0) {
            *(float4*)(out_mu + idx4)  = mu;
            *(float4*)(out_err + idx4) = er;
        }
    }
}

// ---------------- launch ----------------
extern "C" void kernel_launch(void* const* d_in, const int* in_sizes, int n_in,
                              void* d_out, int out_size) {
    const float* mu_upper   = (const float*)d_in[0];
    const float* W          = (const float*)d_in[1];
    const float* a_vec      = (const float*)d_in[2];
    const int*   edge_index = (const int*)d_in[3];
    const int*   src = edge_index;
    const int*   dst = edge_index + N_EDGES;

    float* out       = (float*)d_out;
    float* out_mu    = out;
    float* out_err   = out + N_NODES * OUT_F;
    float* out_alpha = out + 2 * N_NODES * OUT_F;

    const int TPB = 256;
    const int nodeBlocks1 = (N_NODES + TPB - 1) / TPB;
    const int edgeBlocks  = (N_EDGES + TPB - 1) / TPB;
    const int warpNodeBlocks = (N_NODES * 32 + TPB - 1) / TPB;

    init_kernel<<<nodeBlocks1, TPB>>>();
    gemm_kernel<<<1024, TPB>>>(mu_upper, W);
    count_kernel<<<edgeBlocks, TPB>>>(dst);
    scanA_kernel<<<SCAN_BLOCKS, SCAN_TPB>>>();
    scanB_kernel<<<1, 64>>>();
    scanC_kernel<<<nodeBlocks1, TPB>>>();
    scatter_kernel<<<edgeBlocks, TPB>>>(src, dst);

    step0_kernel<<<warpNodeBlocks, TPB>>>(a_vec);

    for (int t = 1; t < N_STEPS; ++t) {
        fused_step_kernel<<<warpNodeBlocks, TPB>>>(
            a_vec, (t - 1) & 1, t & 1, 0, nullptr, nullptr, nullptr);
    }
    fused_step_kernel<<<warpNodeBlocks, TPB>>>(
        a_vec, (N_STEPS - 1) & 1, 0, 1, out_mu, out_err, out_alpha);
}

// round 11
// speedup vs baseline: 1.8166x; 1.0092x over previous
#include <cuda_runtime.h>
#include <cuda_fp16.h>

#define N_NODES 50000
#define N_EDGES 800000
#define IN_F    64
#define OUT_F   32
#define N_STEPS 20
#define LR      0.1f
#define SLOPE   0.2f
#define FULLMASK 0xFFFFFFFFu
#define NEG_INF  __int_as_float(0xFF800000)

#define SCAN_TPB 1024
#define SCAN_BLOCKS ((N_NODES + SCAN_TPB - 1) / SCAN_TPB)   // 49

// ---------------- scratch (device globals; no allocation allowed) ----------------
__device__ __half g_th[N_NODES * OUT_F];      // transformed rows in fp16 (64B/row)
__device__ float g_mu[N_NODES * OUT_F];
__device__ float g_es[2 * N_NODES];   // double-buffered (parity)
__device__ float g_ed[2 * N_NODES];
__device__ int   g_degi[N_NODES];
__device__ int   g_rowstart[N_NODES + 1];
__device__ int   g_fill[N_NODES];
__device__ int   g_bsum[SCAN_BLOCKS];
__device__ int   g_boff[SCAN_BLOCKS];
__device__ int   g_csr_src[N_EDGES];
__device__ int   g_csr_eid[N_EDGES];

__device__ __forceinline__ float leaky(float x) {
    return (x > 0.0f) ? x : SLOPE * x;
}

// load 4 fp16 features (8 bytes) and accumulate into float4 with weight evj
__device__ __forceinline__ void acc_half4(float4& acc, float evj,
                                          const __half* __restrict__ p) {
    uint2 u = *(const uint2*)p;
    __half2 h0 = *reinterpret_cast<__half2*>(&u.x);
    __half2 h1 = *reinterpret_cast<__half2*>(&u.y);
    float2 f0 = __half22float2(h0);
    float2 f1 = __half22float2(h1);
    acc.x = fmaf(evj, f0.x, acc.x);
    acc.y = fmaf(evj, f0.y, acc.y);
    acc.z = fmaf(evj, f1.x, acc.z);
    acc.w = fmaf(evj, f1.y, acc.w);
}

// ---------------- setup kernels ----------------

__global__ void init_kernel() {
    int i = blockIdx.x * blockDim.x + threadIdx.x;
    if (i < N_NODES) g_degi[i] = 0;
}

// transformed = mu_upper @ W^T -> fp16. Warp per node (grid-stride), lane = out feature.
__global__ void gemm_kernel(const float* __restrict__ mu_upper,
                            const float* __restrict__ W) {
    __shared__ float Wt[IN_F][OUT_F];   // Wt[k][f] = W[f*IN_F + k]
    for (int i = threadIdx.x; i < IN_F * OUT_F; i += blockDim.x) {
        int k = i >> 5, f = i & 31;
        Wt[k][f] = W[f * IN_F + k];
    }
    __syncthreads();

    int lane = threadIdx.x & 31;
    int warpsPerGrid = (gridDim.x * blockDim.x) >> 5;
    int w0 = (blockIdx.x * blockDim.x + threadIdx.x) >> 5;

    for (int n = w0; n < N_NODES; n += warpsPerGrid) {
        const float* row = mu_upper + n * IN_F;
        float r0 = row[lane];
        float r1 = row[lane + 32];
        float acc = 0.0f;
#pragma unroll
        for (int k = 0; k < 32; ++k)
            acc = fmaf(__shfl_sync(FULLMASK, r0, k), Wt[k][lane], acc);
#pragma unroll
        for (int k = 0; k < 32; ++k)
            acc = fmaf(__shfl_sync(FULLMASK, r1, k), Wt[32 + k][lane], acc);
        g_th[n * OUT_F + lane] = __float2half(acc);
    }
}

__global__ void count_kernel(const int* __restrict__ dst) {
    int e = blockIdx.x * blockDim.x + threadIdx.x;
    if (e >= N_EDGES) return;
    atomicAdd(&g_degi[dst[e]], 1);
}

__global__ void scanA_kernel() {
    __shared__ int warp_sums[32];
    int tid  = threadIdx.x;
    int lane = tid & 31;
    int wid  = tid >> 5;
    int idx  = blockIdx.x * SCAN_TPB + tid;

    int v = (idx < N_NODES) ? g_degi[idx] : 0;
    int x = v;
#pragma unroll
    for (int off = 1; off < 32; off <<= 1) {
        int y = __shfl_up_sync(FULLMASK, x, off);
        if (lane >= off) x += y;
    }
    if (lane == 31) warp_sums[wid] = x;
    __syncthreads();
    if (wid == 0) {
        int w = warp_sums[lane];
#pragma unroll
        for (int off = 1; off < 32; off <<= 1) {
            int y = __shfl_up_sync(FULLMASK, w, off);
            if (lane >= off) w += y;
        }
        warp_sums[lane] = w;
    }
    __syncthreads();
    int incl = x + ((wid > 0) ? warp_sums[wid - 1] : 0);
    if (idx < N_NODES) g_rowstart[idx] = incl - v;
    if (tid == SCAN_TPB - 1) g_bsum[blockIdx.x] = incl;
}

__global__ void scanB_kernel() {
    __shared__ int s[64];
    int t = threadIdx.x;
    int v = (t < SCAN_BLOCKS) ? g_bsum[t] : 0;
    s[t] = v;
    __syncthreads();
#pragma unroll
    for (int off = 1; off < 64; off <<= 1) {
        int x = (t >= off) ? s[t - off] : 0;
        __syncthreads();
        s[t] += x;
        __syncthreads();
    }
    if (t < SCAN_BLOCKS) g_boff[t] = s[t] - v;
    if (t == 63) g_rowstart[N_NODES] = s[63];
}

__global__ void scanC_kernel() {
    int idx = blockIdx.x * blockDim.x + threadIdx.x;
    if (idx >= N_NODES) return;
    int r = g_rowstart[idx] + g_boff[idx >> 10];
    g_rowstart[idx] = r;
    g_fill[idx] = r;
}

__global__ void scatter_kernel(const int* __restrict__ src,
                               const int* __restrict__ dst) {
    int e = blockIdx.x * blockDim.x + threadIdx.x;
    if (e >= N_EDGES) return;
    int pos = atomicAdd(&g_fill[dst[e]], 1);
    g_csr_src[pos] = src[e];
    g_csr_eid[pos] = e;
}

// ---------------- step 0: uniform-alpha top-down + node update (mu0 = 0) --------
__global__ void step0_kernel(const float* __restrict__ a_vec) {
    int t = blockIdx.x * blockDim.x + threadIdx.x;
    int n = t >> 5;
    int lane = t & 31;
    if (n >= N_NODES) return;
    int q  = lane >> 3;
    int fl = lane & 7;

    int beg = g_rowstart[n], end = g_rowstart[n + 1];
    int deg = end - beg;

    float4 acc = make_float4(0.f, 0.f, 0.f, 0.f);
#pragma unroll 2
    for (int base = 0; base < deg; base += 4) {
        int e = base + q;
        if (e < deg) {
            int s = __ldg(&g_csr_src[beg + e]);
            acc_half4(acc, 1.0f, g_th + s * OUT_F + fl * 4);
        }
    }
#pragma unroll
    for (int off = 8; off <= 16; off <<= 1) {
        acc.x += __shfl_xor_sync(FULLMASK, acc.x, off);
        acc.y += __shfl_xor_sync(FULLMASK, acc.y, off);
        acc.z += __shfl_xor_sync(FULLMASK, acc.z, off);
        acc.w += __shfl_xor_sync(FULLMASK, acc.w, off);
    }
    float inv = 1.0f / ((float)deg + 1e-8f);
    float4 mh = make_float4(fmaxf(acc.x * inv, 0.f), fmaxf(acc.y * inv, 0.f),
                            fmaxf(acc.z * inv, 0.f), fmaxf(acc.w * inv, 0.f));
    const float4 as = *(const float4*)(a_vec + fl * 4);
    const float4 ad = *(const float4*)(a_vec + OUT_F + fl * 4);
    float ps = -(mh.x * as.x + mh.y * as.y + mh.z * as.z + mh.w * as.w);
    float pd = -(mh.x * ad.x + mh.y * ad.y + mh.z * ad.z + mh.w * ad.w);
#pragma unroll
    for (int off = 1; off <= 4; off <<= 1) {
        ps += __shfl_xor_sync(FULLMASK, ps, off);
        pd += __shfl_xor_sync(FULLMASK, pd, off);
    }
    if (lane == 0) {
        g_es[n] = ps;
        g_ed[n] = pd;
    }
    if (q == 0)
        *(float4*)(g_mu + n * OUT_F + fl * 4) =
            make_float4(LR * mh.x, LR * mh.y, LR * mh.z, LR * mh.w);
}

// ---------------- fused step: softmax + aggregate + node update ----------------
// mode 0: intermediate (writes mu, es/ed[out_par]); mode 1: final outputs.
__global__ void __launch_bounds__(256)
fused_step_kernel(const float* __restrict__ a_vec,
                  int in_par, int out_par, int mode,
                  float* __restrict__ out_mu,
                  float* __restrict__ out_err,
                  float* __restrict__ out_alpha) {
    int t = blockIdx.x * blockDim.x + threadIdx.x;
    int n = t >> 5;
    int lane = t & 31;
    if (n >= N_NODES) return;
    int q  = lane >> 3;
    int fl = lane & 7;

    const float* __restrict__ es_in = g_es + in_par * N_NODES;
    const float* __restrict__ ed_in = g_ed + in_par * N_NODES;

    int beg = g_rowstart[n], end = g_rowstart[n + 1];
    int deg = end - beg;
    float ed_n = __ldg(&ed_in[n]);

    float inv;
    float4 acc = make_float4(0.f, 0.f, 0.f, 0.f);

    if (deg <= 64) {
        // -------- score phase: lane per edge, 2-block register cache --------
        int i0 = beg + lane, i1 = i0 + 32;
        int s0 = 0, s1 = 0;
        float sc0 = NEG_INF, sc1 = NEG_INF;
        if (i0 < end) {
            s0 = __ldg(&g_csr_src[i0]);
            sc0 = leaky(__ldg(&es_in[s0]) + ed_n);
        }
        if (i1 < end) {
            s1 = __ldg(&g_csr_src[i1]);
            sc1 = leaky(__ldg(&es_in[s1]) + ed_n);
        }
        float mx = fmaxf(sc0, sc1);
#pragma unroll
        for (int off = 16; off > 0; off >>= 1)
            mx = fmaxf(mx, __shfl_xor_sync(FULLMASK, mx, off));
        if (mx == NEG_INF) mx = 0.0f;    // deg==0 guard

        float ev0 = __expf(sc0 - mx);    // inactive lanes -> exp(-inf)=0
        float ev1 = __expf(sc1 - mx);
        float sm = ev0 + ev1;
#pragma unroll
        for (int off = 16; off > 0; off >>= 1)
            sm += __shfl_xor_sync(FULLMASK, sm, off);
        inv = 1.0f / (sm + 1e-8f);

        // -------- accumulate: 4 edges/iter, quarter per edge, 4 halves/lane --
        if (deg <= 32) {
#pragma unroll 2
            for (int base = 0; base < deg; base += 4) {
                int e = base + q;
                int   sj  = __shfl_sync(FULLMASK, s0,  e & 31);
                float evj = __shfl_sync(FULLMASK, ev0, e & 31);
                if (e < deg)
                    acc_half4(acc, evj, g_th + sj * OUT_F + fl * 4);
            }
        } else {
#pragma unroll 2
            for (int base = 0; base < deg; base += 4) {
                int e = base + q;
                int lsel = e & 31;
                int   sA = __shfl_sync(FULLMASK, s0,  lsel);
                float eA = __shfl_sync(FULLMASK, ev0, lsel);
                int   sB = __shfl_sync(FULLMASK, s1,  lsel);
                float eB = __shfl_sync(FULLMASK, ev1, lsel);
                int   sj  = (e < 32) ? sA : sB;
                float evj = (e < 32) ? eA : eB;
                if (e < deg)
                    acc_half4(acc, evj, g_th + sj * OUT_F + fl * 4);
            }
        }

        if (mode == 1) {
            if (i0 < end) out_alpha[g_csr_eid[i0]] = ev0 * inv;
            if (i1 < end) out_alpha[g_csr_eid[i1]] = ev1 * inv;
        }
    } else {
        // -------- fallback (deg > 64): strided two-pass --------
        float mx = NEG_INF;
        for (int i = beg + lane; i < end; i += 32) {
            int s = __ldg(&g_csr_src[i]);
            mx = fmaxf(mx, leaky(__ldg(&es_in[s]) + ed_n));
        }
#pragma unroll
        for (int off = 16; off > 0; off >>= 1)
            mx = fmaxf(mx, __shfl_xor_sync(FULLMASK, mx, off));

        float sm = 0.0f;
        for (int base = beg; base < end; base += 32) {
            int i = base + lane;
            int s = 0;
            float ev = 0.0f;
            if (i < end) {
                s = __ldg(&g_csr_src[i]);
                ev = __expf(leaky(__ldg(&es_in[s]) + ed_n) - mx);
                sm += ev;
            }
            int cnt = min(32, end - base);
            for (int g = 0; g < cnt; g += 4) {
                int e = g + q;
                int   sj  = __shfl_sync(FULLMASK, s,  e & 31);
                float evj = __shfl_sync(FULLMASK, ev, e & 31);
                if (e < cnt)
                    acc_half4(acc, evj, g_th + sj * OUT_F + fl * 4);
            }
        }
#pragma unroll
        for (int off = 16; off > 0; off >>= 1)
            sm += __shfl_xor_sync(FULLMASK, sm, off);
        inv = 1.0f / (sm + 1e-8f);

        if (mode == 1) {
            for (int i = beg + lane; i < end; i += 32) {
                int s = __ldg(&g_csr_src[i]);
                float ev = __expf(leaky(__ldg(&es_in[s]) + ed_n) - mx);
                out_alpha[g_csr_eid[i]] = ev * inv;
            }
        }
    }

    // -------- reduce acc across quarters --------
#pragma unroll
    for (int off = 8; off <= 16; off <<= 1) {
        acc.x += __shfl_xor_sync(FULLMASK, acc.x, off);
        acc.y += __shfl_xor_sync(FULLMASK, acc.y, off);
        acc.z += __shfl_xor_sync(FULLMASK, acc.z, off);
        acc.w += __shfl_xor_sync(FULLMASK, acc.w, off);
    }

    // -------- fused node update (float4 per lane over features fl*4..+3) ----
    int idx4 = n * OUT_F + fl * 4;
    float4 mh = make_float4(fmaxf(acc.x * inv, 0.f), fmaxf(acc.y * inv, 0.f),
                            fmaxf(acc.z * inv, 0.f), fmaxf(acc.w * inv, 0.f));
    float4 mu = *(const float4*)(g_mu + idx4);
    float4 er = make_float4(mu.x - mh.x, mu.y - mh.y, mu.z - mh.z, mu.w - mh.w);

    if (mode == 0) {
        const float4 as = *(const float4*)(a_vec + fl * 4);
        const float4 ad = *(const float4*)(a_vec + OUT_F + fl * 4);
        float ps = er.x * as.x + er.y * as.y + er.z * as.z + er.w * as.w;
        float pd = er.x * ad.x + er.y * ad.y + er.z * ad.z + er.w * ad.w;
#pragma unroll
        for (int off = 1; off <= 4; off <<= 1) {
            ps += __shfl_xor_sync(FULLMASK, ps, off);
            pd += __shfl_xor_sync(FULLMASK, pd, off);
        }
        if (lane == 0) {
            g_es[out_par * N_NODES + n] = ps;
            g_ed[out_par * N_NODES + n] = pd;
        }
        if (q == 0) {
            float4 mun = make_float4(mu.x - LR * er.x, mu.y - LR * er.y,
                                     mu.z - LR * er.z, mu.w - LR * er.w);
            *(float4*)(g_mu + idx4) = mun;
        }
    } else {
        if (q == 0) {
            *(float4*)(out_mu + idx4)  = mu;
            *(float4*)(out_err + idx4) = er;
        }
    }
}

// ---------------- launch ----------------
extern "C" void kernel_launch(void* const* d_in, const int* in_sizes, int n_in,
                              void* d_out, int out_size) {
    const float* mu_upper   = (const float*)d_in[0];
    const float* W          = (const float*)d_in[1];
    const float* a_vec      = (const float*)d_in[2];
    const int*   edge_index = (const int*)d_in[3];
    const int*   src = edge_index;
    const int*   dst = edge_index + N_EDGES;

    float* out       = (float*)d_out;
    float* out_mu    = out;
    float* out_err   = out + N_NODES * OUT_F;
    float* out_alpha = out + 2 * N_NODES * OUT_F;

    const int TPB = 256;
    const int nodeBlocks1 = (N_NODES + TPB - 1) / TPB;
    const int edgeBlocks  = (N_EDGES + TPB - 1) / TPB;
    const int warpNodeBlocks = (N_NODES * 32 + TPB - 1) / TPB;

    init_kernel<<<nodeBlocks1, TPB>>>();
    gemm_kernel<<<1024, TPB>>>(mu_upper, W);
    count_kernel<<<edgeBlocks, TPB>>>(dst);
    scanA_kernel<<<SCAN_BLOCKS, SCAN_TPB>>>();
    scanB_kernel<<<1, 64>>>();
    scanC_kernel<<<nodeBlocks1, TPB>>>();
    scatter_kernel<<<edgeBlocks, TPB>>>(src, dst);

    step0_kernel<<<warpNodeBlocks, TPB>>>(a_vec);

    for (int t = 1; t < N_STEPS; ++t) {
        fused_step_kernel<<<warpNodeBlocks, TPB>>>(
            a_vec, (t - 1) & 1, t & 1, 0, nullptr, nullptr, nullptr);
    }
    fused_step_kernel<<<warpNodeBlocks, TPB>>>(
        a_vec, (N_STEPS - 1) & 1, 0, 1, out_mu, out_err, out_alpha);
}

// round 12
// speedup vs baseline: 1.9225x; 1.0583x over previous
#include <cuda_runtime.h>
#include <cuda_fp16.h>

#define N_NODES 50000
#define N_EDGES 800000
#define IN_F    64
#define OUT_F   32
#define N_STEPS 20
#define LR      0.1f
#define SLOPE   0.2f
#define FULLMASK 0xFFFFFFFFu
#define NEG_INF  __int_as_float(0xFF800000)

#define SCAN_TPB 1024
#define SCAN_BLOCKS ((N_NODES + SCAN_TPB - 1) / SCAN_TPB)   // 49

// ---------------- scratch (device globals; no allocation allowed) ----------------
__device__ __half g_th[N_NODES * OUT_F];      // transformed rows in fp16 (64B/row)
__device__ float g_mu[N_NODES * OUT_F];
__device__ float g_es[2 * N_NODES];   // double-buffered (parity)
__device__ float g_ed[2 * N_NODES];
__device__ int   g_degi[N_NODES];
__device__ int   g_rowstart[N_NODES + 1];
__device__ int   g_fill[N_NODES];
__device__ int   g_bsum[SCAN_BLOCKS];
__device__ int   g_boff[SCAN_BLOCKS];
__device__ int   g_csr_src[N_EDGES];
__device__ int   g_csr_eid[N_EDGES];

__device__ __forceinline__ float leaky(float x) {
    return (x > 0.0f) ? x : SLOPE * x;
}

// load 4 fp16 features (8 bytes) and accumulate into float4 with weight evj
__device__ __forceinline__ void acc_half4(float4& acc, float evj,
                                          const __half* __restrict__ p) {
    uint2 u = *(const uint2*)p;
    __half2 h0 = *reinterpret_cast<__half2*>(&u.x);
    __half2 h1 = *reinterpret_cast<__half2*>(&u.y);
    float2 f0 = __half22float2(h0);
    float2 f1 = __half22float2(h1);
    acc.x = fmaf(evj, f0.x, acc.x);
    acc.y = fmaf(evj, f0.y, acc.y);
    acc.z = fmaf(evj, f1.x, acc.z);
    acc.w = fmaf(evj, f1.y, acc.w);
}

// ---------------- setup kernels ----------------

__global__ void init_kernel() {
    int i = blockIdx.x * blockDim.x + threadIdx.x;
    if (i < N_NODES) g_degi[i] = 0;
}

// transformed = mu_upper @ W^T -> fp16. Warp per node (grid-stride), lane = out feature.
__global__ void gemm_kernel(const float* __restrict__ mu_upper,
                            const float* __restrict__ W) {
    __shared__ float Wt[IN_F][OUT_F];   // Wt[k][f] = W[f*IN_F + k]
    for (int i = threadIdx.x; i < IN_F * OUT_F; i += blockDim.x) {
        int k = i >> 5, f = i & 31;
        Wt[k][f] = W[f * IN_F + k];
    }
    __syncthreads();

    int lane = threadIdx.x & 31;
    int warpsPerGrid = (gridDim.x * blockDim.x) >> 5;
    int w0 = (blockIdx.x * blockDim.x + threadIdx.x) >> 5;

    for (int n = w0; n < N_NODES; n += warpsPerGrid) {
        const float* row = mu_upper + n * IN_F;
        float r0 = row[lane];
        float r1 = row[lane + 32];
        float acc = 0.0f;
#pragma unroll
        for (int k = 0; k < 32; ++k)
            acc = fmaf(__shfl_sync(FULLMASK, r0, k), Wt[k][lane], acc);
#pragma unroll
        for (int k = 0; k < 32; ++k)
            acc = fmaf(__shfl_sync(FULLMASK, r1, k), Wt[32 + k][lane], acc);
        g_th[n * OUT_F + lane] = __float2half(acc);
    }
}

__global__ void count_kernel(const int* __restrict__ dst) {
    int e = blockIdx.x * blockDim.x + threadIdx.x;
    if (e >= N_EDGES) return;
    atomicAdd(&g_degi[dst[e]], 1);
}

__global__ void scanA_kernel() {
    __shared__ int warp_sums[32];
    int tid  = threadIdx.x;
    int lane = tid & 31;
    int wid  = tid >> 5;
    int idx  = blockIdx.x * SCAN_TPB + tid;

    int v = (idx < N_NODES) ? g_degi[idx] : 0;
    int x = v;
#pragma unroll
    for (int off = 1; off < 32; off <<= 1) {
        int y = __shfl_up_sync(FULLMASK, x, off);
        if (lane >= off) x += y;
    }
    if (lane == 31) warp_sums[wid] = x;
    __syncthreads();
    if (wid == 0) {
        int w = warp_sums[lane];
#pragma unroll
        for (int off = 1; off < 32; off <<= 1) {
            int y = __shfl_up_sync(FULLMASK, w, off);
            if (lane >= off) w += y;
        }
        warp_sums[lane] = w;
    }
    __syncthreads();
    int incl = x + ((wid > 0) ? warp_sums[wid - 1] : 0);
    if (idx < N_NODES) g_rowstart[idx] = incl - v;
    if (tid == SCAN_TPB - 1) g_bsum[blockIdx.x] = incl;
}

__global__ void scanB_kernel() {
    __shared__ int s[64];
    int t = threadIdx.x;
    int v = (t < SCAN_BLOCKS) ? g_bsum[t] : 0;
    s[t] = v;
    __syncthreads();
#pragma unroll
    for (int off = 1; off < 64; off <<= 1) {
        int x = (t >= off) ? s[t - off] : 0;
        __syncthreads();
        s[t] += x;
        __syncthreads();
    }
    if (t < SCAN_BLOCKS) g_boff[t] = s[t] - v;
    if (t == 63) g_rowstart[N_NODES] = s[63];
}

__global__ void scanC_kernel() {
    int idx = blockIdx.x * blockDim.x + threadIdx.x;
    if (idx >= N_NODES) return;
    int r = g_rowstart[idx] + g_boff[idx >> 10];
    g_rowstart[idx] = r;
    g_fill[idx] = r;
}

__global__ void scatter_kernel(const int* __restrict__ src,
                               const int* __restrict__ dst) {
    int e = blockIdx.x * blockDim.x + threadIdx.x;
    if (e >= N_EDGES) return;
    int pos = atomicAdd(&g_fill[dst[e]], 1);
    g_csr_src[pos] = src[e];
    g_csr_eid[pos] = e;
}

// ---------------- step 0: uniform-alpha top-down + node update (mu0 = 0) --------
__global__ void step0_kernel(const float* __restrict__ a_vec) {
    int t = blockIdx.x * blockDim.x + threadIdx.x;
    int n = t >> 5;
    int lane = t & 31;
    if (n >= N_NODES) return;
    int q  = lane >> 3;
    int fl = lane & 7;

    int beg = g_rowstart[n], end = g_rowstart[n + 1];
    int deg = end - beg;

    float4 acc = make_float4(0.f, 0.f, 0.f, 0.f);
#pragma unroll 2
    for (int base = 0; base < deg; base += 4) {
        int e = base + q;
        if (e < deg) {
            int s = __ldg(&g_csr_src[beg + e]);
            acc_half4(acc, 1.0f, g_th + s * OUT_F + fl * 4);
        }
    }
#pragma unroll
    for (int off = 8; off <= 16; off <<= 1) {
        acc.x += __shfl_xor_sync(FULLMASK, acc.x, off);
        acc.y += __shfl_xor_sync(FULLMASK, acc.y, off);
        acc.z += __shfl_xor_sync(FULLMASK, acc.z, off);
        acc.w += __shfl_xor_sync(FULLMASK, acc.w, off);
    }
    float inv = 1.0f / ((float)deg + 1e-8f);
    float4 mh = make_float4(fmaxf(acc.x * inv, 0.f), fmaxf(acc.y * inv, 0.f),
                            fmaxf(acc.z * inv, 0.f), fmaxf(acc.w * inv, 0.f));
    const float4 as = *(const float4*)(a_vec + fl * 4);
    const float4 ad = *(const float4*)(a_vec + OUT_F + fl * 4);
    float ps = -(mh.x * as.x + mh.y * as.y + mh.z * as.z + mh.w * as.w);
    float pd = -(mh.x * ad.x + mh.y * ad.y + mh.z * ad.z + mh.w * ad.w);
#pragma unroll
    for (int off = 1; off <= 4; off <<= 1) {
        ps += __shfl_xor_sync(FULLMASK, ps, off);
        pd += __shfl_xor_sync(FULLMASK, pd, off);
    }
    if (lane == 0) {
        g_es[n] = ps;
        g_ed[n] = pd;
    }
    if (q == 0)
        *(float4*)(g_mu + n * OUT_F + fl * 4) =
            make_float4(LR * mh.x, LR * mh.y, LR * mh.z, LR * mh.w);
}

// ---------------- fused step: softmax + aggregate + node update ----------------
// mode 0: intermediate (writes mu, es/ed[out_par]); mode 1: final outputs.
// Fast path uses a max-free softmax: alpha = exp(s)/sum(exp(s)) — identical
// mathematically (scores are O(1..10), far from overflow) and removes the
// max-reduction tree from the load->accumulate critical path.
__global__ void __launch_bounds__(256)
fused_step_kernel(const float* __restrict__ a_vec,
                  int in_par, int out_par, int mode,
                  float* __restrict__ out_mu,
                  float* __restrict__ out_err,
                  float* __restrict__ out_alpha) {
    int t = blockIdx.x * blockDim.x + threadIdx.x;
    int n = t >> 5;
    int lane = t & 31;
    if (n >= N_NODES) return;
    int q  = lane >> 3;
    int fl = lane & 7;

    const float* __restrict__ es_in = g_es + in_par * N_NODES;
    const float* __restrict__ ed_in = g_ed + in_par * N_NODES;

    int beg = g_rowstart[n], end = g_rowstart[n + 1];
    int deg = end - beg;
    float ed_n = __ldg(&ed_in[n]);

    float inv;
    float4 acc = make_float4(0.f, 0.f, 0.f, 0.f);

    if (deg <= 64) {
        // -------- score phase: lane per edge, 2-block register cache --------
        int i0 = beg + lane, i1 = i0 + 32;
        int s0 = 0, s1 = 0;
        float sc0 = NEG_INF, sc1 = NEG_INF;
        if (i0 < end) {
            s0 = __ldg(&g_csr_src[i0]);
            sc0 = leaky(__ldg(&es_in[s0]) + ed_n);
        }
        if (i1 < end) {
            s1 = __ldg(&g_csr_src[i1]);
            sc1 = leaky(__ldg(&es_in[s1]) + ed_n);
        }

        // max-free: ev available immediately (exp(-inf)=0 for inactive lanes)
        float ev0 = __expf(sc0);
        float ev1 = __expf(sc1);
        float sm = ev0 + ev1;

        // -------- accumulate: starts right away; sum tree overlaps ----------
        if (deg <= 32) {
#pragma unroll 2
            for (int base = 0; base < deg; base += 4) {
                int e = base + q;
                int   sj  = __shfl_sync(FULLMASK, s0,  e & 31);
                float evj = __shfl_sync(FULLMASK, ev0, e & 31);
                if (e < deg)
                    acc_half4(acc, evj, g_th + sj * OUT_F + fl * 4);
            }
        } else {
#pragma unroll 2
            for (int base = 0; base < deg; base += 4) {
                int e = base + q;
                int lsel = e & 31;
                int   sA = __shfl_sync(FULLMASK, s0,  lsel);
                float eA = __shfl_sync(FULLMASK, ev0, lsel);
                int   sB = __shfl_sync(FULLMASK, s1,  lsel);
                float eB = __shfl_sync(FULLMASK, ev1, lsel);
                int   sj  = (e < 32) ? sA : sB;
                float evj = (e < 32) ? eA : eB;
                if (e < deg)
                    acc_half4(acc, evj, g_th + sj * OUT_F + fl * 4);
            }
        }

        // sum reduction (independent of the accumulate loop above)
#pragma unroll
        for (int off = 16; off > 0; off >>= 1)
            sm += __shfl_xor_sync(FULLMASK, sm, off);
        inv = 1.0f / (sm + 1e-8f);

        if (mode == 1) {
            if (i0 < end) out_alpha[g_csr_eid[i0]] = ev0 * inv;
            if (i1 < end) out_alpha[g_csr_eid[i1]] = ev1 * inv;
        }
    } else {
        // -------- fallback (deg > 64): max-based strided two-pass --------
        float mx = NEG_INF;
        for (int i = beg + lane; i < end; i += 32) {
            int s = __ldg(&g_csr_src[i]);
            mx = fmaxf(mx, leaky(__ldg(&es_in[s]) + ed_n));
        }
#pragma unroll
        for (int off = 16; off > 0; off >>= 1)
            mx = fmaxf(mx, __shfl_xor_sync(FULLMASK, mx, off));

        float sm = 0.0f;
        for (int base = beg; base < end; base += 32) {
            int i = base + lane;
            int s = 0;
            float ev = 0.0f;
            if (i < end) {
                s = __ldg(&g_csr_src[i]);
                ev = __expf(leaky(__ldg(&es_in[s]) + ed_n) - mx);
                sm += ev;
            }
            int cnt = min(32, end - base);
            for (int g = 0; g < cnt; g += 4) {
                int e = g + q;
                int   sj  = __shfl_sync(FULLMASK, s,  e & 31);
                float evj = __shfl_sync(FULLMASK, ev, e & 31);
                if (e < cnt)
                    acc_half4(acc, evj, g_th + sj * OUT_F + fl * 4);
            }
        }
#pragma unroll
        for (int off = 16; off > 0; off >>= 1)
            sm += __shfl_xor_sync(FULLMASK, sm, off);
        inv = 1.0f / (sm + 1e-8f);

        if (mode == 1) {
            for (int i = beg + lane; i < end; i += 32) {
                int s = __ldg(&g_csr_src[i]);
                float ev = __expf(leaky(__ldg(&es_in[s]) + ed_n) - mx);
                out_alpha[g_csr_eid[i]] = ev * inv;
            }
        }
    }

    // -------- reduce acc across quarters --------
#pragma unroll
    for (int off = 8; off <= 16; off <<= 1) {
        acc.x += __shfl_xor_sync(FULLMASK, acc.x, off);
        acc.y += __shfl_xor_sync(FULLMASK, acc.y, off);
        acc.z += __shfl_xor_sync(FULLMASK, acc.z, off);
        acc.w += __shfl_xor_sync(FULLMASK, acc.w, off);
    }

    // -------- fused node update (float4 per lane over features fl*4..+3) ----
    int idx4 = n * OUT_F + fl * 4;
    float4 mh = make_float4(fmaxf(acc.x * inv, 0.f), fmaxf(acc.y * inv, 0.f),
                            fmaxf(acc.z * inv, 0.f), fmaxf(acc.w * inv, 0.f));
    float4 mu = *(const float4*)(g_mu + idx4);
    float4 er = make_float4(mu.x - mh.x, mu.y - mh.y, mu.z - mh.z, mu.w - mh.w);

    if (mode == 0) {
        const float4 as = *(const float4*)(a_vec + fl * 4);
        const float4 ad = *(const float4*)(a_vec + OUT_F + fl * 4);
        float ps = er.x * as.x + er.y * as.y + er.z * as.z + er.w * as.w;
        float pd = er.x * ad.x + er.y * ad.y + er.z * ad.z + er.w * ad.w;
#pragma unroll
        for (int off = 1; off <= 4; off <<= 1) {
            ps += __shfl_xor_sync(FULLMASK, ps, off);
            pd += __shfl_xor_sync(FULLMASK, pd, off);
        }
        if (lane == 0) {
            g_es[out_par * N_NODES + n] = ps;
            g_ed[out_par * N_NODES + n] = pd;
        }
        if (q == 0) {
            float4 mun = make_float4(mu.x - LR * er.x, mu.y - LR * er.y,
                                     mu.z - LR * er.z, mu.w - LR * er.w);
            *(float4*)(g_mu + idx4) = mun;
        }
    } else {
        if (q == 0) {
            *(float4*)(out_mu + idx4)  = mu;
            *(float4*)(out_err + idx4) = er;
        }
    }
}

// ---------------- launch ----------------
extern "C" void kernel_launch(void* const* d_in, const int* in_sizes, int n_in,
                              void* d_out, int out_size) {
    const float* mu_upper   = (const float*)d_in[0];
    const float* W          = (const float*)d_in[1];
    const float* a_vec      = (const float*)d_in[2];
    const int*   edge_index = (const int*)d_in[3];
    const int*   src = edge_index;
    const int*   dst = edge_index + N_EDGES;

    float* out       = (float*)d_out;
    float* out_mu    = out;
    float* out_err   = out + N_NODES * OUT_F;
    float* out_alpha = out + 2 * N_NODES * OUT_F;

    const int TPB = 256;
    const int nodeBlocks1 = (N_NODES + TPB - 1) / TPB;
    const int edgeBlocks  = (N_EDGES + TPB - 1) / TPB;
    const int warpNodeBlocks = (N_NODES * 32 + TPB - 1) / TPB;

    init_kernel<<<nodeBlocks1, TPB>>>();
    gemm_kernel<<<1024, TPB>>>(mu_upper, W);
    count_kernel<<<edgeBlocks, TPB>>>(dst);
    scanA_kernel<<<SCAN_BLOCKS, SCAN_TPB>>>();
    scanB_kernel<<<1, 64>>>();
    scanC_kernel<<<nodeBlocks1, TPB>>>();
    scatter_kernel<<<edgeBlocks, TPB>>>(src, dst);

    step0_kernel<<<warpNodeBlocks, TPB>>>(a_vec);

    for (int t = 1; t < N_STEPS; ++t) {
        fused_step_kernel<<<warpNodeBlocks, TPB>>>(
            a_vec, (t - 1) & 1, t & 1, 0, nullptr, nullptr, nullptr);
    }
    fused_step_kernel<<<warpNodeBlocks, TPB>>>(
        a_vec, (N_STEPS - 1) & 1, 0, 1, out_mu, out_err, out_alpha);
}

// round 13
// speedup vs baseline: 2.1207x; 1.1031x over previous
#include <cuda_runtime.h>
#include <cuda_fp16.h>

#define N_NODES 50000
#define N_EDGES 800000
#define IN_F    64
#define OUT_F   32
#define N_STEPS 20
#define LR      0.1f
#define SLOPE   0.2f
#define FULLMASK 0xFFFFFFFFu

#define SCAN_TPB 1024
#define SCAN_BLOCKS ((N_NODES + SCAN_TPB - 1) / SCAN_TPB)   // 49

// two nodes per warp
#define N_WARPS ((N_NODES + 1) / 2)                          // 25000

// ---------------- scratch (device globals; no allocation allowed) ----------------
__device__ __half g_th[N_NODES * OUT_F];      // transformed rows in fp16 (64B/row)
__device__ float g_mu[N_NODES * OUT_F];
__device__ float g_es[2 * N_NODES];   // double-buffered (parity)
__device__ float g_ed[2 * N_NODES];
__device__ int   g_degi[N_NODES];
__device__ int   g_rowstart[N_NODES + 1];
__device__ int   g_fill[N_NODES];
__device__ int   g_bsum[SCAN_BLOCKS];
__device__ int   g_boff[SCAN_BLOCKS];
__device__ int   g_csr_src[N_EDGES];
__device__ int   g_csr_eid[N_EDGES];

__device__ __forceinline__ float leaky(float x) {
    return (x > 0.0f) ? x : SLOPE * x;
}

// load 4 fp16 features (8 bytes) and accumulate into float4 with weight evj
__device__ __forceinline__ void acc_half4(float4& acc, float evj,
                                          const __half* __restrict__ p) {
    uint2 u = *(const uint2*)p;
    __half2 h0 = *reinterpret_cast<__half2*>(&u.x);
    __half2 h1 = *reinterpret_cast<__half2*>(&u.y);
    float2 f0 = __half22float2(h0);
    float2 f1 = __half22float2(h1);
    acc.x = fmaf(evj, f0.x, acc.x);
    acc.y = fmaf(evj, f0.y, acc.y);
    acc.z = fmaf(evj, f1.x, acc.z);
    acc.w = fmaf(evj, f1.y, acc.w);
}

// ---------------- setup kernels ----------------

__global__ void init_kernel() {
    int i = blockIdx.x * blockDim.x + threadIdx.x;
    if (i < N_NODES) g_degi[i] = 0;
}

// transformed = mu_upper @ W^T -> fp16. Warp per node (grid-stride), lane = out feature.
__global__ void gemm_kernel(const float* __restrict__ mu_upper,
                            const float* __restrict__ W) {
    __shared__ float Wt[IN_F][OUT_F];   // Wt[k][f] = W[f*IN_F + k]
    for (int i = threadIdx.x; i < IN_F * OUT_F; i += blockDim.x) {
        int k = i >> 5, f = i & 31;
        Wt[k][f] = W[f * IN_F + k];
    }
    __syncthreads();

    int lane = threadIdx.x & 31;
    int warpsPerGrid = (gridDim.x * blockDim.x) >> 5;
    int w0 = (blockIdx.x * blockDim.x + threadIdx.x) >> 5;

    for (int n = w0; n < N_NODES; n += warpsPerGrid) {
        const float* row = mu_upper + n * IN_F;
        float r0 = row[lane];
        float r1 = row[lane + 32];
        float acc = 0.0f;
#pragma unroll
        for (int k = 0; k < 32; ++k)
            acc = fmaf(__shfl_sync(FULLMASK, r0, k), Wt[k][lane], acc);
#pragma unroll
        for (int k = 0; k < 32; ++k)
            acc = fmaf(__shfl_sync(FULLMASK, r1, k), Wt[32 + k][lane], acc);
        g_th[n * OUT_F + lane] = __float2half(acc);
    }
}

__global__ void count_kernel(const int* __restrict__ dst) {
    int e = blockIdx.x * blockDim.x + threadIdx.x;
    if (e >= N_EDGES) return;
    atomicAdd(&g_degi[dst[e]], 1);
}

__global__ void scanA_kernel() {
    __shared__ int warp_sums[32];
    int tid  = threadIdx.x;
    int lane = tid & 31;
    int wid  = tid >> 5;
    int idx  = blockIdx.x * SCAN_TPB + tid;

    int v = (idx < N_NODES) ? g_degi[idx] : 0;
    int x = v;
#pragma unroll
    for (int off = 1; off < 32; off <<= 1) {
        int y = __shfl_up_sync(FULLMASK, x, off);
        if (lane >= off) x += y;
    }
    if (lane == 31) warp_sums[wid] = x;
    __syncthreads();
    if (wid == 0) {
        int w = warp_sums[lane];
#pragma unroll
        for (int off = 1; off < 32; off <<= 1) {
            int y = __shfl_up_sync(FULLMASK, w, off);
            if (lane >= off) w += y;
        }
        warp_sums[lane] = w;
    }
    __syncthreads();
    int incl = x + ((wid > 0) ? warp_sums[wid - 1] : 0);
    if (idx < N_NODES) g_rowstart[idx] = incl - v;
    if (tid == SCAN_TPB - 1) g_bsum[blockIdx.x] = incl;
}

__global__ void scanB_kernel() {
    __shared__ int s[64];
    int t = threadIdx.x;
    int v = (t < SCAN_BLOCKS) ? g_bsum[t] : 0;
    s[t] = v;
    __syncthreads();
#pragma unroll
    for (int off = 1; off < 64; off <<= 1) {
        int x = (t >= off) ? s[t - off] : 0;
        __syncthreads();
        s[t] += x;
        __syncthreads();
    }
    if (t < SCAN_BLOCKS) g_boff[t] = s[t] - v;
    if (t == 63) g_rowstart[N_NODES] = s[63];
}

__global__ void scanC_kernel() {
    int idx = blockIdx.x * blockDim.x + threadIdx.x;
    if (idx >= N_NODES) return;
    int r = g_rowstart[idx] + g_boff[idx >> 10];
    g_rowstart[idx] = r;
    g_fill[idx] = r;
}

__global__ void scatter_kernel(const int* __restrict__ src,
                               const int* __restrict__ dst) {
    int e = blockIdx.x * blockDim.x + threadIdx.x;
    if (e >= N_EDGES) return;
    int pos = atomicAdd(&g_fill[dst[e]], 1);
    g_csr_src[pos] = src[e];
    g_csr_eid[pos] = e;
}

// ---------------- step 0: uniform-alpha top-down + node update (mu0 = 0) --------
// two nodes per warp: lanes 0-15 -> node 2w, lanes 16-31 -> node 2w+1
__global__ void __launch_bounds__(256)
step0_kernel(const float* __restrict__ a_vec) {
    int t = blockIdx.x * blockDim.x + threadIdx.x;
    int wid = t >> 5;
    if (wid >= N_WARPS) return;
    int lane = t & 31;
    int h  = lane >> 4;          // which node in warp
    int hl = lane & 15;          // lane within half
    int eq = hl >> 3;            // edge-quarter (0/1)
    int fl = hl & 7;             // float4 feature slice
    int n = 2 * wid + h;         // N_NODES even -> always valid

    int beg = g_rowstart[n], end = g_rowstart[n + 1];
    int deg = end - beg;
    int degO = __shfl_xor_sync(FULLMASK, deg, 16);
    int rounds = (max(deg, degO) + 15) >> 4;

    float4 acc = make_float4(0.f, 0.f, 0.f, 0.f);
    for (int r = 0; r < rounds; ++r) {
        int eb = r << 4;
        int s = 0;
        if (eb + hl < deg) s = __ldg(&g_csr_src[beg + eb + hl]);
#pragma unroll
        for (int g = 0; g < 8; ++g) {
            int e = (g << 1) + eq;
            int sj = __shfl_sync(FULLMASK, s, (h << 4) + e);
            if (eb + e < deg)
                acc_half4(acc, 1.0f, g_th + sj * OUT_F + fl * 4);
        }
    }
    // reduce across eq (within half)
    acc.x += __shfl_xor_sync(FULLMASK, acc.x, 8);
    acc.y += __shfl_xor_sync(FULLMASK, acc.y, 8);
    acc.z += __shfl_xor_sync(FULLMASK, acc.z, 8);
    acc.w += __shfl_xor_sync(FULLMASK, acc.w, 8);

    float inv = 1.0f / ((float)deg + 1e-8f);
    float4 mh = make_float4(fmaxf(acc.x * inv, 0.f), fmaxf(acc.y * inv, 0.f),
                            fmaxf(acc.z * inv, 0.f), fmaxf(acc.w * inv, 0.f));
    const float4 as = *(const float4*)(a_vec + fl * 4);
    const float4 ad = *(const float4*)(a_vec + OUT_F + fl * 4);
    float ps = -(mh.x * as.x + mh.y * as.y + mh.z * as.z + mh.w * as.w);
    float pd = -(mh.x * ad.x + mh.y * ad.y + mh.z * ad.z + mh.w * ad.w);
#pragma unroll
    for (int off = 1; off <= 4; off <<= 1) {
        ps += __shfl_xor_sync(FULLMASK, ps, off);
        pd += __shfl_xor_sync(FULLMASK, pd, off);
    }
    if (hl == 0) {
        g_es[n] = ps;
        g_ed[n] = pd;
    }
    if (eq == 0)
        *(float4*)(g_mu + n * OUT_F + fl * 4) =
            make_float4(LR * mh.x, LR * mh.y, LR * mh.z, LR * mh.w);
}

// ---------------- fused step: softmax + aggregate + node update ----------------
// two nodes per warp; max-free softmax (scores O(1..10), far from overflow).
// mode 0: intermediate (writes mu, es/ed[out_par]); mode 1: final outputs.
__global__ void __launch_bounds__(256)
fused_step_kernel(const float* __restrict__ a_vec,
                  int in_par, int out_par, int mode,
                  float* __restrict__ out_mu,
                  float* __restrict__ out_err,
                  float* __restrict__ out_alpha) {
    int t = blockIdx.x * blockDim.x + threadIdx.x;
    int wid = t >> 5;
    if (wid >= N_WARPS) return;
    int lane = t & 31;
    int h  = lane >> 4;
    int hl = lane & 15;
    int eq = hl >> 3;
    int fl = hl & 7;
    int n = 2 * wid + h;

    const float* __restrict__ es_in = g_es + in_par * N_NODES;
    const float* __restrict__ ed_in = g_ed + in_par * N_NODES;

    int beg = g_rowstart[n], end = g_rowstart[n + 1];
    int deg = end - beg;
    float ed_n = __ldg(&ed_in[n]);

    int degO = __shfl_xor_sync(FULLMASK, deg, 16);
    int rounds = (max(deg, degO) + 15) >> 4;

    float sm = 0.0f;
    float4 acc = make_float4(0.f, 0.f, 0.f, 0.f);

    for (int r = 0; r < rounds; ++r) {
        int eb = r << 4;
        int s = 0;
        float ev = 0.0f;
        if (eb + hl < deg) {
            s = __ldg(&g_csr_src[beg + eb + hl]);
            ev = __expf(leaky(__ldg(&es_in[s]) + ed_n));
        }
        sm += ev;
#pragma unroll
        for (int g = 0; g < 8; ++g) {
            int e = (g << 1) + eq;
            int src_lane = (h << 4) + e;
            int   sj  = __shfl_sync(FULLMASK, s,  src_lane);
            float evj = __shfl_sync(FULLMASK, ev, src_lane);
            if (eb + e < deg)
                acc_half4(acc, evj, g_th + sj * OUT_F + fl * 4);
        }
    }

    // sum reduction within half (4 levels)
#pragma unroll
    for (int off = 8; off >= 1; off >>= 1)
        sm += __shfl_xor_sync(FULLMASK, sm, off);
    float inv = 1.0f / (sm + 1e-8f);

    // reduce acc across eq (1 level, within half)
    acc.x += __shfl_xor_sync(FULLMASK, acc.x, 8);
    acc.y += __shfl_xor_sync(FULLMASK, acc.y, 8);
    acc.z += __shfl_xor_sync(FULLMASK, acc.z, 8);
    acc.w += __shfl_xor_sync(FULLMASK, acc.w, 8);

    if (mode == 1) {
        // emit alpha (recompute scores; one-time final pass)
        for (int r = 0; r < rounds; ++r) {
            int i = beg + (r << 4) + hl;
            if ((r << 4) + hl < deg) {
                int s = __ldg(&g_csr_src[i]);
                float ev = __expf(leaky(__ldg(&es_in[s]) + ed_n));
                out_alpha[g_csr_eid[i]] = ev * inv;
            }
        }
    }

    // -------- fused node update (float4 per lane over features fl*4..+3) ----
    int idx4 = n * OUT_F + fl * 4;
    float4 mh = make_float4(fmaxf(acc.x * inv, 0.f), fmaxf(acc.y * inv, 0.f),
                            fmaxf(acc.z * inv, 0.f), fmaxf(acc.w * inv, 0.f));
    float4 mu = *(const float4*)(g_mu + idx4);
    float4 er = make_float4(mu.x - mh.x, mu.y - mh.y, mu.z - mh.z, mu.w - mh.w);

    if (mode == 0) {
        const float4 as = *(const float4*)(a_vec + fl * 4);
        const float4 ad = *(const float4*)(a_vec + OUT_F + fl * 4);
        float ps = er.x * as.x + er.y * as.y + er.z * as.z + er.w * as.w;
        float pd = er.x * ad.x + er.y * ad.y + er.z * ad.z + er.w * ad.w;
#pragma unroll
        for (int off = 1; off <= 4; off <<= 1) {
            ps += __shfl_xor_sync(FULLMASK, ps, off);
            pd += __shfl_xor_sync(FULLMASK, pd, off);
        }
        if (hl == 0) {
            g_es[out_par * N_NODES + n] = ps;
            g_ed[out_par * N_NODES + n] = pd;
        }
        if (eq == 0) {
            float4 mun = make_float4(mu.x - LR * er.x, mu.y - LR * er.y,
                                     mu.z - LR * er.z, mu.w - LR * er.w);
            *(float4*)(g_mu + idx4) = mun;
        }
    } else {
        if (eq == 0) {
            *(float4*)(out_mu + idx4)  = mu;
            *(float4*)(out_err + idx4) = er;
        }
    }
}

// ---------------- launch ----------------
extern "C" void kernel_launch(void* const* d_in, const int* in_sizes, int n_in,
                              void* d_out, int out_size) {
    const float* mu_upper   = (const float*)d_in[0];
    const float* W          = (const float*)d_in[1];
    const float* a_vec      = (const float*)d_in[2];
    const int*   edge_index = (const int*)d_in[3];
    const int*   src = edge_index;
    const int*   dst = edge_index + N_EDGES;

    float* out       = (float*)d_out;
    float* out_mu    = out;
    float* out_err   = out + N_NODES * OUT_F;
    float* out_alpha = out + 2 * N_NODES * OUT_F;

    const int TPB = 256;
    const int nodeBlocks1 = (N_NODES + TPB - 1) / TPB;
    const int edgeBlocks  = (N_EDGES + TPB - 1) / TPB;
    const int warp2Blocks = (N_WARPS * 32 + TPB - 1) / TPB;   // 3125

    init_kernel<<<nodeBlocks1, TPB>>>();
    gemm_kernel<<<1024, TPB>>>(mu_upper, W);
    count_kernel<<<edgeBlocks, TPB>>>(dst);
    scanA_kernel<<<SCAN_BLOCKS, SCAN_TPB>>>();
    scanB_kernel<<<1, 64>>>();
    scanC_kernel<<<nodeBlocks1, TPB>>>();
    scatter_kernel<<<edgeBlocks, TPB>>>(src, dst);

    step0_kernel<<<warp2Blocks, TPB>>>(a_vec);

    for (int t = 1; t < N_STEPS; ++t) {
        fused_step_kernel<<<warp2Blocks, TPB>>>(
            a_vec, (t - 1) & 1, t & 1, 0, nullptr, nullptr, nullptr);
    }
    fused_step_kernel<<<warp2Blocks, TPB>>>(
        a_vec, (N_STEPS - 1) & 1, 0, 1, out_mu, out_err, out_alpha);
}